// round 13
// baseline (speedup 1.0000x reference)
#include <cuda_runtime.h>
#include <math.h>

#define B_    8
#define C_    512
#define N_    2048
#define KH    9
#define PAD   4
#define MLPH  2048

// ---------------- scratch (device globals: no allocations allowed) ----------
__device__ float g_qln[B_ * C_ * N_];
__device__ float g_kln[B_ * C_ * N_];
__device__ float g_qp [B_ * C_ * N_];
__device__ float g_kp [B_ * C_ * N_];
__device__ float g_vp [B_ * C_ * N_];
__device__ float g_xln[B_ * C_ * N_];
__device__ float g_h  [B_ * MLPH * N_];
// tf32-rounded operand copies
__device__ float g_wqT [C_ * C_];
__device__ float g_wkT [C_ * C_];
__device__ float g_wvT [C_ * C_];
__device__ float g_w1r [C_ * MLPH];
__device__ float g_w2r [MLPH * C_];
__device__ float g_keyr[B_ * C_ * N_];

__device__ __forceinline__ float tf32r(float x) {
    unsigned r; asm("cvt.rna.tf32.f32 %0, %1;" : "=r"(r) : "f"(x));
    return __uint_as_float(r);
}

// ---------------- prep: transpose [M,K] -> [K,M] with tf32 rounding ---------
__global__ void transpose_round(const float* __restrict__ src,
                                float* __restrict__ dst, int M, int K) {
    __shared__ float tile[32][33];
    int k0 = blockIdx.x * 32, m0 = blockIdx.y * 32;
    int tx = threadIdx.x, ty = threadIdx.y;   // 32 x 8
#pragma unroll
    for (int j = 0; j < 32; j += 8)
        tile[ty + j][tx] = src[(size_t)(m0 + ty + j) * K + k0 + tx];
    __syncthreads();
#pragma unroll
    for (int j = 0; j < 32; j += 8)
        dst[(size_t)(k0 + ty + j) * M + m0 + tx] = tf32r(tile[tx][ty + j]);
}

// ---------------- prep: elementwise tf32 round-copy -------------------------
__global__ void round_copy(const float4* __restrict__ src,
                           float4* __restrict__ dst, int n4) {
    int i = blockIdx.x * blockDim.x + threadIdx.x;
    if (i < n4) {
        float4 v = src[i];
        dst[i] = make_float4(tf32r(v.x), tf32r(v.y), tf32r(v.z), tf32r(v.w));
    }
}

// ---------------- fused (optional add) + channel LayerNorm, 2-phase tiled ---
// Block = (32 n) x (8 c-groups) = 256 threads; grid = (N/32, B, nz).
// z selects the (x, e, out) set so q-LN and k-LN run in ONE launch.
template<bool HASE>
__global__ __launch_bounds__(256)
void add_ln_kernel(const float* __restrict__ x0, const float* __restrict__ e0,
                   float* __restrict__ out0,
                   const float* __restrict__ x1, const float* __restrict__ e1,
                   float* __restrict__ out1,
                   const float* __restrict__ g, const float* __restrict__ bb) {
    __shared__ float ps [8][33];
    __shared__ float ps2[8][33];
    __shared__ float smean[32], sinv[32];

    const float* x  = blockIdx.z ? x1  : x0;
    const float* e  = blockIdx.z ? e1  : e0;
    float*       out= blockIdx.z ? out1: out0;

    int tx = threadIdx.x & 31;          // n within tile (warp-coalesced)
    int ty = threadIdx.x >> 5;          // c-group 0..7
    int n  = blockIdx.x * 32 + tx;
    int b  = blockIdx.y;
    const size_t base = (size_t)b * C_ * N_ + n;

    float s = 0.f, s2 = 0.f;
#pragma unroll 8
    for (int c = ty; c < C_; c += 8) {
        float v = x[base + (size_t)c * N_];
        if (HASE) v += e[base + (size_t)c * N_];
        s += v; s2 += v * v;
    }
    ps[ty][tx] = s; ps2[ty][tx] = s2;
    __syncthreads();
    if (threadIdx.x < 32) {
        float a = 0.f, a2 = 0.f;
#pragma unroll
        for (int i = 0; i < 8; i++) { a += ps[i][threadIdx.x]; a2 += ps2[i][threadIdx.x]; }
        float mean = a * (1.f / C_);
        float var  = a2 * (1.f / C_) - mean * mean;
        smean[threadIdx.x] = mean;
        sinv [threadIdx.x] = rsqrtf(var + 1e-5f);
    }
    __syncthreads();
    float mean = smean[tx], inv = sinv[tx];
#pragma unroll 8
    for (int c = ty; c < C_; c += 8) {
        float v = x[base + (size_t)c * N_];
        if (HASE) v += e[base + (size_t)c * N_];
        out[base + (size_t)c * N_] =
            tf32r((v - mean) * inv * __ldg(&g[c]) + __ldg(&bb[c]));
    }
}

// ---------------- cp.async helpers ------------------------------------------
__device__ __forceinline__ void cp16(void* smem_dst, const void* gmem_src) {
    unsigned d = (unsigned)__cvta_generic_to_shared(smem_dst);
    asm volatile("cp.async.cg.shared.global [%0], [%1], 16;" :: "r"(d), "l"(gmem_src));
}

// ---------------- TF32 tensor-core GEMM body, 3-stage cp.async --------------
// Y[m,n] = sum_k W[k,m] * X[k,n]  (pointers pre-offset per batch by wrappers).
// BM=BN=128, BK=16. 128 threads = 4 warps (2x2), warp tile 64x64,
// per warp 4x8 grid of mma.m16n8k8 (tf32 in, fp32 accum).
// EPI: 0 = +bias, 1 = gelu(+bias) exact + tf32-round store, 2 = +bias+residual.
#define GEMM_BK   16
#define GEMM_LDS  136
#define SMEM_GEMM (3 * 2 * GEMM_BK * GEMM_LDS * 4)   // 52224 bytes

extern __shared__ float dyn_smem[];

template<int EPI>
__device__ __forceinline__
void gemm_body(const float* __restrict__ W, const float* __restrict__ Xb,
               const float* __restrict__ bias, const float* __restrict__ Rb,
               float* __restrict__ Yb, int M, int N, int K) {
    const int BK = GEMM_BK, LDS_ = GEMM_LDS;
    float (*As)[BK][LDS_] = (float (*)[BK][LDS_])dyn_smem;                  // 3 stages [k][m]
    float (*Bs)[BK][LDS_] = (float (*)[BK][LDS_])(dyn_smem + 3 * BK * LDS_); // 3 stages [k][n]

    int t    = threadIdx.x;
    int lane = t & 31;
    int warp = t >> 5;                  // 0..3
    int gid  = lane >> 2;
    int tig  = lane & 3;
    int wm   = (warp & 1) * 64;
    int wn   = (warp >> 1) * 64;

    int n0 = blockIdx.x * 128;
    int m0 = blockIdx.y * 128;

    float c[4][8][4];
#pragma unroll
    for (int i = 0; i < 4; i++)
#pragma unroll
        for (int j = 0; j < 8; j++)
#pragma unroll
            for (int r = 0; r < 4; r++) c[i][j][r] = 0.f;

    auto load_tiles = [&](int s, int k0) {
#pragma unroll
        for (int i = 0; i < 4; i++) {
            int idx = t + 128 * i;          // 0..511 16B-chunks
            int kk  = idx >> 5;
            int q   = (idx & 31) << 2;
            cp16(&As[s][kk][q], &W [(size_t)(k0 + kk) * M + m0 + q]);
            cp16(&Bs[s][kk][q], &Xb[(size_t)(k0 + kk) * N + n0 + q]);
        }
        asm volatile("cp.async.commit_group;");
    };

    int iters = K / BK;
    load_tiles(0, 0);
    load_tiles(1, BK);

    int s = 0;
    for (int it = 0; it < iters; ++it) {
        if (it) __syncthreads();            // WAR: readers of the reused stage done
        if (it + 2 < iters) {
            load_tiles((it + 2) % 3, (it + 2) * BK);
            asm volatile("cp.async.wait_group 2;");   // oldest (stage s) complete
        } else {
            asm volatile("cp.async.wait_group 0;");
        }
        __syncthreads();                    // visibility of stage s to all warps

#pragma unroll
        for (int ks = 0; ks < BK; ks += 8) {
            unsigned bfrag[8][2];
#pragma unroll
            for (int ni = 0; ni < 8; ni++) {
                int nb = wn + 8 * ni + gid;
                bfrag[ni][0] = __float_as_uint(Bs[s][ks + tig    ][nb]);
                bfrag[ni][1] = __float_as_uint(Bs[s][ks + tig + 4][nb]);
            }
#pragma unroll
            for (int mi = 0; mi < 4; mi++) {
                int mb = wm + 16 * mi + gid;
                unsigned a0 = __float_as_uint(As[s][ks + tig    ][mb]);
                unsigned a1 = __float_as_uint(As[s][ks + tig    ][mb + 8]);
                unsigned a2 = __float_as_uint(As[s][ks + tig + 4][mb]);
                unsigned a3 = __float_as_uint(As[s][ks + tig + 4][mb + 8]);
#pragma unroll
                for (int ni = 0; ni < 8; ni++) {
                    asm volatile(
                        "mma.sync.aligned.m16n8k8.row.col.f32.tf32.tf32.f32 "
                        "{%0,%1,%2,%3}, {%4,%5,%6,%7}, {%8,%9}, {%0,%1,%2,%3};"
                        : "+f"(c[mi][ni][0]), "+f"(c[mi][ni][1]),
                          "+f"(c[mi][ni][2]), "+f"(c[mi][ni][3])
                        : "r"(a0), "r"(a1), "r"(a2), "r"(a3),
                          "r"(bfrag[ni][0]), "r"(bfrag[ni][1]));
                }
            }
        }
        s = (s + 1) == 3 ? 0 : s + 1;
    }

    // ---- epilogue ----
#pragma unroll
    for (int mi = 0; mi < 4; mi++) {
        int mA = m0 + wm + 16 * mi + gid;
        int mB = mA + 8;
        float bvA = __ldg(&bias[mA]);
        float bvB = __ldg(&bias[mB]);
#pragma unroll
        for (int ni = 0; ni < 8; ni++) {
            int n = n0 + wn + 8 * ni + 2 * tig;
            float v0 = c[mi][ni][0] + bvA;
            float v1 = c[mi][ni][1] + bvA;
            float v2 = c[mi][ni][2] + bvB;
            float v3 = c[mi][ni][3] + bvB;
            if (EPI == 1) {   // exact gelu, then tf32-round (feeds fc2)
                v0 = tf32r(0.5f * v0 * (1.f + erff(v0 * 0.70710678118654752f)));
                v1 = tf32r(0.5f * v1 * (1.f + erff(v1 * 0.70710678118654752f)));
                v2 = tf32r(0.5f * v2 * (1.f + erff(v2 * 0.70710678118654752f)));
                v3 = tf32r(0.5f * v3 * (1.f + erff(v3 * 0.70710678118654752f)));
            }
            if (EPI == 2) {
                float2 rA = *(const float2*)&Rb[(size_t)mA * N + n];
                float2 rB = *(const float2*)&Rb[(size_t)mB * N + n];
                v0 += rA.x; v1 += rA.y; v2 += rB.x; v3 += rB.y;
            }
            *(float2*)&Yb[(size_t)mA * N + n] = make_float2(v0, v1);
            *(float2*)&Yb[(size_t)mB * N + n] = make_float2(v2, v3);
        }
    }
}

// Batched conv wrapper: z = set*8 + b, one launch for all 3 convs x 8 batches.
struct ConvParams {
    const float* W[3];
    const float* X[3];
    const float* bias[3];
    float*       Y[3];
};

__global__ __launch_bounds__(128)
void conv_gemm(ConvParams p) {
    int z = blockIdx.z, set = z >> 3, b = z & 7;
    gemm_body<0>(p.W[set], p.X[set] + (size_t)b * C_ * N_, p.bias[set], nullptr,
                 p.Y[set] + (size_t)b * C_ * N_, C_, N_, C_);
}

__global__ __launch_bounds__(128)
void gemm_fc1(const float* __restrict__ W, const float* __restrict__ X,
              const float* __restrict__ bias, float* __restrict__ Y) {
    int b = blockIdx.z;
    gemm_body<1>(W, X + (size_t)b * C_ * N_, bias, nullptr,
                 Y + (size_t)b * MLPH * N_, MLPH, N_, C_);
}

__global__ __launch_bounds__(128)
void gemm_fc2(const float* __restrict__ W, const float* __restrict__ X,
              const float* __restrict__ bias, const float* __restrict__ res,
              float* __restrict__ Y) {
    int b = blockIdx.z;
    gemm_body<2>(W, X + (size_t)b * MLPH * N_, bias, res + (size_t)b * C_ * N_,
                 Y + (size_t)b * C_ * N_, C_, N_, MLPH);
}

// ---------------- fused windowed attention, split-C (256 threads) -----------
// Block: 128 n-positions; thread halves ty=0/1 each handle 256 channels.
// Phase 1: partial QK window dots -> smem reduce -> softmax*scale.
// Phase 2: each half aggregates V and writes its own 256 output channels.
__global__ __launch_bounds__(256)
void attn_kernel(const float* __restrict__ q, const float* __restrict__ k,
                 const float* __restrict__ v, const float* __restrict__ query,
                 float* __restrict__ out) {
    __shared__ float s1[2][8][128];
    __shared__ float s2[2][8][136];
    __shared__ float swt[KH][128];
    int tid = threadIdx.x;
    int tx  = tid & 127;
    int ty  = tid >> 7;
    int n0  = blockIdx.x * 128;
    int b   = blockIdx.y;
    int n   = n0 + tx;
    const size_t base = (size_t)b * C_ * N_;

    float acc[KH];
#pragma unroll
    for (int j = 0; j < KH; j++) acc[j] = 0.f;

    int cbeg = ty * 256;
    for (int c0 = cbeg; c0 < cbeg + 256; c0 += 8) {
#pragma unroll
        for (int j = 0; j < 8; j++) {
            s1[ty][j][tx] = q[base + (size_t)(c0 + j) * N_ + n];
            int nn = n0 + tx - PAD;
            s2[ty][j][tx] = (nn >= 0 && nn < N_) ? k[base + (size_t)(c0 + j) * N_ + nn] : 0.f;
        }
        if (tx < 8) {
#pragma unroll
            for (int j = 0; j < 8; j++) {
                int nn = n0 + 128 + tx - PAD;
                s2[ty][j][128 + tx] = (nn < N_) ? k[base + (size_t)(c0 + j) * N_ + nn] : 0.f;
            }
        }
        __syncthreads();
#pragma unroll
        for (int cc = 0; cc < 8; cc++) {
            float qv = s1[ty][cc][tx];
#pragma unroll
            for (int j = 0; j < KH; j++) acc[j] += qv * s2[ty][cc][tx + j];
        }
        __syncthreads();
    }

    // reduce the two halves, softmax (ty==0), broadcast weights
    if (ty == 1) {
#pragma unroll
        for (int j = 0; j < KH; j++) swt[j][tx] = acc[j];
    }
    __syncthreads();
    if (ty == 0) {
#pragma unroll
        for (int j = 0; j < KH; j++) acc[j] += swt[j][tx];
        float mx = acc[0];
#pragma unroll
        for (int j = 1; j < KH; j++) mx = fmaxf(mx, acc[j]);
        float sum = 0.f;
#pragma unroll
        for (int j = 0; j < KH; j++) { acc[j] = expf(acc[j] - mx); sum += acc[j]; }
        float inv = 0.044194173824159216f / sum;   // 512^-0.5 / sum
#pragma unroll
        for (int j = 0; j < KH; j++) swt[j][tx] = acc[j] * inv;
    }
    __syncthreads();
    float w[KH];
#pragma unroll
    for (int j = 0; j < KH; j++) w[j] = swt[j][tx];

    for (int c0 = cbeg; c0 < cbeg + 256; c0 += 8) {
#pragma unroll
        for (int j = 0; j < 8; j++) {
            int nn = n0 + tx - PAD;
            s2[ty][j][tx] = (nn >= 0 && nn < N_) ? v[base + (size_t)(c0 + j) * N_ + nn] : 0.f;
        }
        if (tx < 8) {
#pragma unroll
            for (int j = 0; j < 8; j++) {
                int nn = n0 + 128 + tx - PAD;
                s2[ty][j][128 + tx] = (nn < N_) ? v[base + (size_t)(c0 + j) * N_ + nn] : 0.f;
            }
        }
        __syncthreads();
#pragma unroll
        for (int cc = 0; cc < 8; cc++) {
            float r = 0.f;
#pragma unroll
            for (int j = 0; j < KH; j++) r += w[j] * s2[ty][cc][tx + j];
            size_t idx = base + (size_t)(c0 + cc) * N_ + n;
            out[idx] = query[idx] + r;
        }
        __syncthreads();
    }
}

// ---------------- launch -----------------------------------------------------
extern "C" void kernel_launch(void* const* d_in, const int* in_sizes, int n_in,
                              void* d_out, int out_size) {
    const float* query = (const float*)d_in[0];
    const float* key   = (const float*)d_in[1];
    const float* qe    = (const float*)d_in[2];
    const float* ke    = (const float*)d_in[3];
    const float* wq    = (const float*)d_in[4];
    const float* bq    = (const float*)d_in[5];
    const float* wk    = (const float*)d_in[6];
    const float* bk    = (const float*)d_in[7];
    const float* wv    = (const float*)d_in[8];
    const float* bv    = (const float*)d_in[9];
    const float* gn    = (const float*)d_in[10];
    const float* bn    = (const float*)d_in[11];
    const float* gn2   = (const float*)d_in[12];
    const float* bn2   = (const float*)d_in[13];
    const float* w1    = (const float*)d_in[14];
    const float* b1    = (const float*)d_in[15];
    const float* w2    = (const float*)d_in[16];
    const float* b2    = (const float*)d_in[17];
    float* out = (float*)d_out;

    float *qln, *kln, *qp, *kp, *vp, *xln, *hbuf;
    float *wqT, *wkT, *wvT, *w1r, *w2r, *keyr;
    cudaGetSymbolAddress((void**)&qln,  g_qln);
    cudaGetSymbolAddress((void**)&kln,  g_kln);
    cudaGetSymbolAddress((void**)&qp,   g_qp);
    cudaGetSymbolAddress((void**)&kp,   g_kp);
    cudaGetSymbolAddress((void**)&vp,   g_vp);
    cudaGetSymbolAddress((void**)&xln,  g_xln);
    cudaGetSymbolAddress((void**)&hbuf, g_h);
    cudaGetSymbolAddress((void**)&wqT,  g_wqT);
    cudaGetSymbolAddress((void**)&wkT,  g_wkT);
    cudaGetSymbolAddress((void**)&wvT,  g_wvT);
    cudaGetSymbolAddress((void**)&w1r,  g_w1r);
    cudaGetSymbolAddress((void**)&w2r,  g_w2r);
    cudaGetSymbolAddress((void**)&keyr, g_keyr);

    // opt-in to >48KB dynamic smem for the GEMM kernels (idempotent)
    cudaFuncSetAttribute(conv_gemm, cudaFuncAttributeMaxDynamicSharedMemorySize, SMEM_GEMM);
    cudaFuncSetAttribute(gemm_fc1,  cudaFuncAttributeMaxDynamicSharedMemorySize, SMEM_GEMM);
    cudaFuncSetAttribute(gemm_fc2,  cudaFuncAttributeMaxDynamicSharedMemorySize, SMEM_GEMM);

    // 0) operand prep: tf32-round every GEMM input that isn't produced rounded
    dim3 tb(32, 8);
    transpose_round<<<dim3(C_ / 32, C_ / 32), tb>>>(wq, wqT, C_, C_);
    transpose_round<<<dim3(C_ / 32, C_ / 32), tb>>>(wk, wkT, C_, C_);
    transpose_round<<<dim3(C_ / 32, C_ / 32), tb>>>(wv, wvT, C_, C_);
    round_copy<<<(C_ * MLPH / 4 + 255) / 256, 256>>>((const float4*)w1, (float4*)w1r, C_ * MLPH / 4);
    round_copy<<<(MLPH * C_ / 4 + 255) / 256, 256>>>((const float4*)w2, (float4*)w2r, MLPH * C_ / 4);
    round_copy<<<(B_ * C_ * N_ / 4 + 255) / 256, 256>>>((const float4*)key, (float4*)keyr, B_ * C_ * N_ / 4);

    // 1) q/k: add pos-embed + shared LayerNorm (both in ONE launch via z)
    add_ln_kernel<true><<<dim3(N_ / 32, B_, 2), 256>>>(
        query, qe, qln, key, ke, kln, gn, bn);

    // 2) all three 1x1 convs in ONE launch (v uses raw key, rounded copy)
    ConvParams cp;
    cp.W[0] = wqT;  cp.W[1] = wkT;  cp.W[2] = wvT;
    cp.X[0] = qln;  cp.X[1] = kln;  cp.X[2] = keyr;
    cp.bias[0] = bq; cp.bias[1] = bk; cp.bias[2] = bv;
    cp.Y[0] = qp;   cp.Y[1] = kp;   cp.Y[2] = vp;
    conv_gemm<<<dim3(N_ / 128, C_ / 128, 3 * B_), 128, SMEM_GEMM>>>(cp);

    // 3) windowed attention + residual  -> d_out holds x
    attn_kernel<<<dim3(N_ / 128, B_), 256>>>(qp, kp, vp, query, out);

    // 4) MLP: pre-LN (rounded), fc1+gelu (rounded out), fc2+residual
    add_ln_kernel<false><<<dim3(N_ / 32, B_, 1), 256>>>(
        out, nullptr, xln, nullptr, nullptr, nullptr, gn2, bn2);
    gemm_fc1<<<dim3(N_ / 128, MLPH / 128, B_), 128, SMEM_GEMM>>>(w1r, xln,  b1, hbuf);
    gemm_fc2<<<dim3(N_ / 128, C_   / 128, B_), 128, SMEM_GEMM>>>(w2r, hbuf, b2, out, out);
}

// round 14
// speedup vs baseline: 1.4329x; 1.4329x over previous
#include <cuda_runtime.h>
#include <math.h>

#define B_    8
#define C_    512
#define N_    2048
#define KH    9
#define PAD   4
#define MLPH  2048

// ---------------- scratch (device globals: no allocations allowed) ----------
__device__ float g_qln[B_ * C_ * N_];
__device__ float g_kln[B_ * C_ * N_];
__device__ float g_qp [B_ * C_ * N_];
__device__ float g_kp [B_ * C_ * N_];
__device__ float g_vp [B_ * C_ * N_];
__device__ float g_xln[B_ * C_ * N_];
__device__ float g_h  [B_ * MLPH * N_];
// tf32-rounded operand copies
__device__ float g_wqT [C_ * C_];
__device__ float g_wkT [C_ * C_];
__device__ float g_wvT [C_ * C_];
__device__ float g_w1r [C_ * MLPH];
__device__ float g_w2r [MLPH * C_];
__device__ float g_keyr[B_ * C_ * N_];

__device__ __forceinline__ float tf32r(float x) {
    unsigned r; asm("cvt.rna.tf32.f32 %0, %1;" : "=r"(r) : "f"(x));
    return __uint_as_float(r);
}

// ---------------- prep: transpose [M,K] -> [K,M] with tf32 rounding ---------
__global__ void transpose_round(const float* __restrict__ src,
                                float* __restrict__ dst, int M, int K) {
    __shared__ float tile[32][33];
    int k0 = blockIdx.x * 32, m0 = blockIdx.y * 32;
    int tx = threadIdx.x, ty = threadIdx.y;   // 32 x 8
#pragma unroll
    for (int j = 0; j < 32; j += 8)
        tile[ty + j][tx] = src[(size_t)(m0 + ty + j) * K + k0 + tx];
    __syncthreads();
#pragma unroll
    for (int j = 0; j < 32; j += 8)
        dst[(size_t)(k0 + ty + j) * M + m0 + tx] = tf32r(tile[tx][ty + j]);
}

// ---------------- prep: elementwise tf32 round-copy -------------------------
__global__ void round_copy(const float4* __restrict__ src,
                           float4* __restrict__ dst, int n4) {
    int i = blockIdx.x * blockDim.x + threadIdx.x;
    if (i < n4) {
        float4 v = src[i];
        dst[i] = make_float4(tf32r(v.x), tf32r(v.y), tf32r(v.z), tf32r(v.w));
    }
}

// ---------------- fused (optional add) + channel LayerNorm, 2-phase tiled ---
// Block = (32 n) x (8 c-groups) = 256 threads; grid = (N/32, B, nz).
// z selects the (x, e, out) set so q-LN and k-LN run in ONE launch.
template<bool HASE>
__global__ __launch_bounds__(256)
void add_ln_kernel(const float* __restrict__ x0, const float* __restrict__ e0,
                   float* __restrict__ out0,
                   const float* __restrict__ x1, const float* __restrict__ e1,
                   float* __restrict__ out1,
                   const float* __restrict__ g, const float* __restrict__ bb) {
    __shared__ float ps [8][33];
    __shared__ float ps2[8][33];
    __shared__ float smean[32], sinv[32];

    const float* x  = blockIdx.z ? x1  : x0;
    const float* e  = blockIdx.z ? e1  : e0;
    float*       out= blockIdx.z ? out1: out0;

    int tx = threadIdx.x & 31;          // n within tile (warp-coalesced)
    int ty = threadIdx.x >> 5;          // c-group 0..7
    int n  = blockIdx.x * 32 + tx;
    int b  = blockIdx.y;
    const size_t base = (size_t)b * C_ * N_ + n;

    float s = 0.f, s2 = 0.f;
#pragma unroll 8
    for (int c = ty; c < C_; c += 8) {
        float v = x[base + (size_t)c * N_];
        if (HASE) v += e[base + (size_t)c * N_];
        s += v; s2 += v * v;
    }
    ps[ty][tx] = s; ps2[ty][tx] = s2;
    __syncthreads();
    if (threadIdx.x < 32) {
        float a = 0.f, a2 = 0.f;
#pragma unroll
        for (int i = 0; i < 8; i++) { a += ps[i][threadIdx.x]; a2 += ps2[i][threadIdx.x]; }
        float mean = a * (1.f / C_);
        float var  = a2 * (1.f / C_) - mean * mean;
        smean[threadIdx.x] = mean;
        sinv [threadIdx.x] = rsqrtf(var + 1e-5f);
    }
    __syncthreads();
    float mean = smean[tx], inv = sinv[tx];
#pragma unroll 8
    for (int c = ty; c < C_; c += 8) {
        float v = x[base + (size_t)c * N_];
        if (HASE) v += e[base + (size_t)c * N_];
        out[base + (size_t)c * N_] =
            tf32r((v - mean) * inv * __ldg(&g[c]) + __ldg(&bb[c]));
    }
}

// ---------------- cp.async helpers ------------------------------------------
__device__ __forceinline__ void cp16(void* smem_dst, const void* gmem_src) {
    unsigned d = (unsigned)__cvta_generic_to_shared(smem_dst);
    asm volatile("cp.async.cg.shared.global [%0], [%1], 16;" :: "r"(d), "l"(gmem_src));
}

// ---------------- TF32 tensor-core GEMM body, 2-stage cp.async --------------
// (EXACT round-11 winning mainloop: static smem, one barrier per K-iter.)
// Y[m,n] = sum_k W[k,m] * X[k,n]  (pointers pre-offset per batch by wrappers).
// BM=BN=128, BK=16. 128 threads = 4 warps (2x2), warp tile 64x64,
// per warp 4x8 grid of mma.m16n8k8 (tf32 in, fp32 accum). LDS/mma = 1.0.
// EPI: 0 = +bias, 1 = gelu(+bias) exact + tf32-round store, 2 = +bias+residual.
template<int EPI>
__device__ __forceinline__
void gemm_body(const float* __restrict__ W, const float* __restrict__ Xb,
               const float* __restrict__ bias, const float* __restrict__ Rb,
               float* __restrict__ Yb, int M, int N, int K) {
    const int BK = 16;
    const int LDS_ = 136;                     // 136 % 32 == 8 -> conflict-free frags
    __shared__ alignas(16) float As[2][BK][LDS_];   // [k][m]
    __shared__ alignas(16) float Bs[2][BK][LDS_];   // [k][n]

    int t    = threadIdx.x;
    int lane = t & 31;
    int warp = t >> 5;                  // 0..3
    int gid  = lane >> 2;
    int tig  = lane & 3;
    int wm   = (warp & 1) * 64;
    int wn   = (warp >> 1) * 64;

    int n0 = blockIdx.x * 128;
    int m0 = blockIdx.y * 128;

    float c[4][8][4];
#pragma unroll
    for (int i = 0; i < 4; i++)
#pragma unroll
        for (int j = 0; j < 8; j++)
#pragma unroll
            for (int r = 0; r < 4; r++) c[i][j][r] = 0.f;

    auto load_tiles = [&](int s, int k0) {
#pragma unroll
        for (int i = 0; i < 4; i++) {
            int idx = t + 128 * i;          // 0..511 16B-chunks
            int kk  = idx >> 5;
            int q   = (idx & 31) << 2;
            cp16(&As[s][kk][q], &W [(size_t)(k0 + kk) * M + m0 + q]);
            cp16(&Bs[s][kk][q], &Xb[(size_t)(k0 + kk) * N + n0 + q]);
        }
        asm volatile("cp.async.commit_group;");
    };

    load_tiles(0, 0);
    int s = 0;
    for (int k0 = 0; k0 < K; k0 += BK) {
        if (k0 + BK < K) {
            load_tiles(s ^ 1, k0 + BK);
            asm volatile("cp.async.wait_group 1;");
        } else {
            asm volatile("cp.async.wait_group 0;");
        }
        __syncthreads();

#pragma unroll
        for (int ks = 0; ks < BK; ks += 8) {
            unsigned bfrag[8][2];
#pragma unroll
            for (int ni = 0; ni < 8; ni++) {
                int nb = wn + 8 * ni + gid;
                bfrag[ni][0] = __float_as_uint(Bs[s][ks + tig    ][nb]);
                bfrag[ni][1] = __float_as_uint(Bs[s][ks + tig + 4][nb]);
            }
#pragma unroll
            for (int mi = 0; mi < 4; mi++) {
                int mb = wm + 16 * mi + gid;
                unsigned a0 = __float_as_uint(As[s][ks + tig    ][mb]);
                unsigned a1 = __float_as_uint(As[s][ks + tig    ][mb + 8]);
                unsigned a2 = __float_as_uint(As[s][ks + tig + 4][mb]);
                unsigned a3 = __float_as_uint(As[s][ks + tig + 4][mb + 8]);
#pragma unroll
                for (int ni = 0; ni < 8; ni++) {
                    asm volatile(
                        "mma.sync.aligned.m16n8k8.row.col.f32.tf32.tf32.f32 "
                        "{%0,%1,%2,%3}, {%4,%5,%6,%7}, {%8,%9}, {%0,%1,%2,%3};"
                        : "+f"(c[mi][ni][0]), "+f"(c[mi][ni][1]),
                          "+f"(c[mi][ni][2]), "+f"(c[mi][ni][3])
                        : "r"(a0), "r"(a1), "r"(a2), "r"(a3),
                          "r"(bfrag[ni][0]), "r"(bfrag[ni][1]));
                }
            }
        }
        __syncthreads();
        s ^= 1;
    }

    // ---- epilogue ----
#pragma unroll
    for (int mi = 0; mi < 4; mi++) {
        int mA = m0 + wm + 16 * mi + gid;
        int mB = mA + 8;
        float bvA = __ldg(&bias[mA]);
        float bvB = __ldg(&bias[mB]);
#pragma unroll
        for (int ni = 0; ni < 8; ni++) {
            int n = n0 + wn + 8 * ni + 2 * tig;
            float v0 = c[mi][ni][0] + bvA;
            float v1 = c[mi][ni][1] + bvA;
            float v2 = c[mi][ni][2] + bvB;
            float v3 = c[mi][ni][3] + bvB;
            if (EPI == 1) {   // exact gelu, then tf32-round (feeds fc2)
                v0 = tf32r(0.5f * v0 * (1.f + erff(v0 * 0.70710678118654752f)));
                v1 = tf32r(0.5f * v1 * (1.f + erff(v1 * 0.70710678118654752f)));
                v2 = tf32r(0.5f * v2 * (1.f + erff(v2 * 0.70710678118654752f)));
                v3 = tf32r(0.5f * v3 * (1.f + erff(v3 * 0.70710678118654752f)));
            }
            if (EPI == 2) {
                float2 rA = *(const float2*)&Rb[(size_t)mA * N + n];
                float2 rB = *(const float2*)&Rb[(size_t)mB * N + n];
                v0 += rA.x; v1 += rA.y; v2 += rB.x; v3 += rB.y;
            }
            *(float2*)&Yb[(size_t)mA * N + n] = make_float2(v0, v1);
            *(float2*)&Yb[(size_t)mB * N + n] = make_float2(v2, v3);
        }
    }
}

// Batched conv wrapper: z = set*8 + b, one launch for all 3 convs x 8 batches.
struct ConvParams {
    const float* W[3];
    const float* X[3];
    const float* bias[3];
    float*       Y[3];
};

__global__ __launch_bounds__(128)
void conv_gemm(ConvParams p) {
    int z = blockIdx.z, set = z >> 3, b = z & 7;
    gemm_body<0>(p.W[set], p.X[set] + (size_t)b * C_ * N_, p.bias[set], nullptr,
                 p.Y[set] + (size_t)b * C_ * N_, C_, N_, C_);
}

__global__ __launch_bounds__(128)
void gemm_fc1(const float* __restrict__ W, const float* __restrict__ X,
              const float* __restrict__ bias, float* __restrict__ Y) {
    int b = blockIdx.z;
    gemm_body<1>(W, X + (size_t)b * C_ * N_, bias, nullptr,
                 Y + (size_t)b * MLPH * N_, MLPH, N_, C_);
}

__global__ __launch_bounds__(128)
void gemm_fc2(const float* __restrict__ W, const float* __restrict__ X,
              const float* __restrict__ bias, const float* __restrict__ res,
              float* __restrict__ Y) {
    int b = blockIdx.z;
    gemm_body<2>(W, X + (size_t)b * MLPH * N_, bias, res + (size_t)b * C_ * N_,
                 Y + (size_t)b * C_ * N_, C_, N_, MLPH);
}

// ---------------- fused windowed attention, split-C (256 threads) -----------
// Block: 128 n-positions; thread halves ty=0/1 each handle 256 channels.
// Phase 1: partial QK window dots -> smem reduce -> softmax*scale.
// Phase 2: each half aggregates V and writes its own 256 output channels.
__global__ __launch_bounds__(256)
void attn_kernel(const float* __restrict__ q, const float* __restrict__ k,
                 const float* __restrict__ v, const float* __restrict__ query,
                 float* __restrict__ out) {
    __shared__ float s1[2][8][128];
    __shared__ float s2[2][8][136];
    __shared__ float swt[KH][128];
    int tid = threadIdx.x;
    int tx  = tid & 127;
    int ty  = tid >> 7;
    int n0  = blockIdx.x * 128;
    int b   = blockIdx.y;
    int n   = n0 + tx;
    const size_t base = (size_t)b * C_ * N_;

    float acc[KH];
#pragma unroll
    for (int j = 0; j < KH; j++) acc[j] = 0.f;

    int cbeg = ty * 256;
    for (int c0 = cbeg; c0 < cbeg + 256; c0 += 8) {
#pragma unroll
        for (int j = 0; j < 8; j++) {
            s1[ty][j][tx] = q[base + (size_t)(c0 + j) * N_ + n];
            int nn = n0 + tx - PAD;
            s2[ty][j][tx] = (nn >= 0 && nn < N_) ? k[base + (size_t)(c0 + j) * N_ + nn] : 0.f;
        }
        if (tx < 8) {
#pragma unroll
            for (int j = 0; j < 8; j++) {
                int nn = n0 + 128 + tx - PAD;
                s2[ty][j][128 + tx] = (nn < N_) ? k[base + (size_t)(c0 + j) * N_ + nn] : 0.f;
            }
        }
        __syncthreads();
#pragma unroll
        for (int cc = 0; cc < 8; cc++) {
            float qv = s1[ty][cc][tx];
#pragma unroll
            for (int j = 0; j < KH; j++) acc[j] += qv * s2[ty][cc][tx + j];
        }
        __syncthreads();
    }

    // reduce the two halves, softmax (ty==0), broadcast weights
    if (ty == 1) {
#pragma unroll
        for (int j = 0; j < KH; j++) swt[j][tx] = acc[j];
    }
    __syncthreads();
    if (ty == 0) {
#pragma unroll
        for (int j = 0; j < KH; j++) acc[j] += swt[j][tx];
        float mx = acc[0];
#pragma unroll
        for (int j = 1; j < KH; j++) mx = fmaxf(mx, acc[j]);
        float sum = 0.f;
#pragma unroll
        for (int j = 0; j < KH; j++) { acc[j] = expf(acc[j] - mx); sum += acc[j]; }
        float inv = 0.044194173824159216f / sum;   // 512^-0.5 / sum
#pragma unroll
        for (int j = 0; j < KH; j++) swt[j][tx] = acc[j] * inv;
    }
    __syncthreads();
    float w[KH];
#pragma unroll
    for (int j = 0; j < KH; j++) w[j] = swt[j][tx];

    for (int c0 = cbeg; c0 < cbeg + 256; c0 += 8) {
#pragma unroll
        for (int j = 0; j < 8; j++) {
            int nn = n0 + tx - PAD;
            s2[ty][j][tx] = (nn >= 0 && nn < N_) ? v[base + (size_t)(c0 + j) * N_ + nn] : 0.f;
        }
        if (tx < 8) {
#pragma unroll
            for (int j = 0; j < 8; j++) {
                int nn = n0 + 128 + tx - PAD;
                s2[ty][j][128 + tx] = (nn < N_) ? v[base + (size_t)(c0 + j) * N_ + nn] : 0.f;
            }
        }
        __syncthreads();
#pragma unroll
        for (int cc = 0; cc < 8; cc++) {
            float r = 0.f;
#pragma unroll
            for (int j = 0; j < KH; j++) r += w[j] * s2[ty][cc][tx + j];
            size_t idx = base + (size_t)(c0 + cc) * N_ + n;
            out[idx] = query[idx] + r;
        }
        __syncthreads();
    }
}

// ---------------- launch -----------------------------------------------------
extern "C" void kernel_launch(void* const* d_in, const int* in_sizes, int n_in,
                              void* d_out, int out_size) {
    const float* query = (const float*)d_in[0];
    const float* key   = (const float*)d_in[1];
    const float* qe    = (const float*)d_in[2];
    const float* ke    = (const float*)d_in[3];
    const float* wq    = (const float*)d_in[4];
    const float* bq    = (const float*)d_in[5];
    const float* wk    = (const float*)d_in[6];
    const float* bk    = (const float*)d_in[7];
    const float* wv    = (const float*)d_in[8];
    const float* bv    = (const float*)d_in[9];
    const float* gn    = (const float*)d_in[10];
    const float* bn    = (const float*)d_in[11];
    const float* gn2   = (const float*)d_in[12];
    const float* bn2   = (const float*)d_in[13];
    const float* w1    = (const float*)d_in[14];
    const float* b1    = (const float*)d_in[15];
    const float* w2    = (const float*)d_in[16];
    const float* b2    = (const float*)d_in[17];
    float* out = (float*)d_out;

    float *qln, *kln, *qp, *kp, *vp, *xln, *hbuf;
    float *wqT, *wkT, *wvT, *w1r, *w2r, *keyr;
    cudaGetSymbolAddress((void**)&qln,  g_qln);
    cudaGetSymbolAddress((void**)&kln,  g_kln);
    cudaGetSymbolAddress((void**)&qp,   g_qp);
    cudaGetSymbolAddress((void**)&kp,   g_kp);
    cudaGetSymbolAddress((void**)&vp,   g_vp);
    cudaGetSymbolAddress((void**)&xln,  g_xln);
    cudaGetSymbolAddress((void**)&hbuf, g_h);
    cudaGetSymbolAddress((void**)&wqT,  g_wqT);
    cudaGetSymbolAddress((void**)&wkT,  g_wkT);
    cudaGetSymbolAddress((void**)&wvT,  g_wvT);
    cudaGetSymbolAddress((void**)&w1r,  g_w1r);
    cudaGetSymbolAddress((void**)&w2r,  g_w2r);
    cudaGetSymbolAddress((void**)&keyr, g_keyr);

    // 0) operand prep: tf32-round every GEMM input that isn't produced rounded
    dim3 tb(32, 8);
    transpose_round<<<dim3(C_ / 32, C_ / 32), tb>>>(wq, wqT, C_, C_);
    transpose_round<<<dim3(C_ / 32, C_ / 32), tb>>>(wk, wkT, C_, C_);
    transpose_round<<<dim3(C_ / 32, C_ / 32), tb>>>(wv, wvT, C_, C_);
    round_copy<<<(C_ * MLPH / 4 + 255) / 256, 256>>>((const float4*)w1, (float4*)w1r, C_ * MLPH / 4);
    round_copy<<<(MLPH * C_ / 4 + 255) / 256, 256>>>((const float4*)w2, (float4*)w2r, MLPH * C_ / 4);
    round_copy<<<(B_ * C_ * N_ / 4 + 255) / 256, 256>>>((const float4*)key, (float4*)keyr, B_ * C_ * N_ / 4);

    // 1) q/k: add pos-embed + shared LayerNorm (both in ONE launch via z)
    add_ln_kernel<true><<<dim3(N_ / 32, B_, 2), 256>>>(
        query, qe, qln, key, ke, kln, gn, bn);

    // 2) all three 1x1 convs in ONE launch (v uses raw key, rounded copy)
    ConvParams cp;
    cp.W[0] = wqT;  cp.W[1] = wkT;  cp.W[2] = wvT;
    cp.X[0] = qln;  cp.X[1] = kln;  cp.X[2] = keyr;
    cp.bias[0] = bq; cp.bias[1] = bk; cp.bias[2] = bv;
    cp.Y[0] = qp;   cp.Y[1] = kp;   cp.Y[2] = vp;
    conv_gemm<<<dim3(N_ / 128, C_ / 128, 3 * B_), 128>>>(cp);

    // 3) windowed attention + residual  -> d_out holds x
    attn_kernel<<<dim3(N_ / 128, B_), 256>>>(qp, kp, vp, query, out);

    // 4) MLP: pre-LN (rounded), fc1+gelu (rounded out), fc2+residual
    add_ln_kernel<false><<<dim3(N_ / 32, B_, 1), 256>>>(
        out, nullptr, xln, nullptr, nullptr, nullptr, gn2, bn2);
    gemm_fc1<<<dim3(N_ / 128, MLPH / 128, B_), 128>>>(w1r, xln,  b1, hbuf);
    gemm_fc2<<<dim3(N_ / 128, C_   / 128, B_), 128>>>(w2r, hbuf, b2, out, out);
}